// round 1
// baseline (speedup 1.0000x reference)
#include <cuda_runtime.h>
#include <math.h>

// Fixed problem shapes
#define BB 2
#define VV 3
#define CC 16
#define HH 128
#define WW 160
#define DD 48
#define HWW (HH*WW)            // 20480
#define NPIX (BB*HWW)          // 40960
#define BDHW (BB*DD*HWW)       // 1966080
#define NV (VV-1)              // 2 source views

// Output layout (concatenated float32 outputs in reference return order)
#define OFF_DEPTH 0
#define OFF_CONF  (NPIX)                   // 40960
#define OFF_PROB  (2*NPIX)                 // 81920
#define OFF_VW    (2*NPIX + BDHW)          // 2048000
// total out = 2129920

// -------- scratch (device globals; no allocation allowed) --------
__device__ float g_feat_t[(size_t)BB*VV*HWW*CC];   // [b][v][h][w][c]
__device__ float g_sim[(size_t)NV*BDHW];           // [view][b][d][h][w]
__device__ float g_vw[(size_t)NV*NPIX];            // [view][b][h][w]
__device__ float g_simil[BDHW];                    // combined similarity
__device__ float g_cost[BDHW];                     // conv output
__device__ float g_proj[NV*BB*12];                 // per (view,b): rot 9 + trans 3
__device__ float g_mlp[177];                       // fw0[16] fc0[16] fw1[128] fc1[8] fw2[8] fb2
__device__ float g_reg[28];                        // reg_w[27] + reg_b

// ======================= prep: matrices + weight folding =======================
__device__ void mat4_mul(const double* A, const double* B, double* Cm) {
    for (int r = 0; r < 4; r++)
        for (int c = 0; c < 4; c++) {
            double s = 0.0;
            for (int k = 0; k < 4; k++) s += A[r*4+k] * B[k*4+c];
            Cm[r*4+c] = s;
        }
}

// p points at proj_matrices[b][v] = [2][4][4] (E then K). out = compose.
__device__ void compose_proj(const float* p, double* out) {
    const float* E = p;
    const float* K = p + 16;
    for (int i = 0; i < 16; i++) out[i] = (double)E[i];
    for (int r = 0; r < 3; r++)
        for (int c = 0; c < 4; c++) {
            double s = 0.0;
            for (int k = 0; k < 3; k++) s += (double)K[r*4+k] * (double)E[k*4+c];
            out[r*4+c] = s;
        }
}

__device__ void inv4(const double* A, double* out) {
    double M[4][8];
    for (int i = 0; i < 4; i++)
        for (int j = 0; j < 4; j++) { M[i][j] = A[i*4+j]; M[i][4+j] = (i == j) ? 1.0 : 0.0; }
    for (int col = 0; col < 4; col++) {
        int piv = col;
        for (int r = col + 1; r < 4; r++)
            if (fabs(M[r][col]) > fabs(M[piv][col])) piv = r;
        if (piv != col)
            for (int j = 0; j < 8; j++) { double t = M[col][j]; M[col][j] = M[piv][j]; M[piv][j] = t; }
        double pv = M[col][col];
        for (int j = 0; j < 8; j++) M[col][j] /= pv;
        for (int r = 0; r < 4; r++) {
            if (r == col) continue;
            double f = M[r][col];
            for (int j = 0; j < 8; j++) M[r][j] -= f * M[col][j];
        }
    }
    for (int i = 0; i < 4; i++)
        for (int j = 0; j < 4; j++) out[i*4+j] = M[i][4+j];
}

__global__ void prep_kernel(const float* proj,
                            const float* w0, const float* g0, const float* b0,
                            const float* m0, const float* v0,
                            const float* w1, const float* g1, const float* b1,
                            const float* m1, const float* v1,
                            const float* w2, const float* b2,
                            const float* reg_w, const float* reg_b) {
    if (blockIdx.x != 0 || threadIdx.x != 0) return;
    for (int b = 0; b < BB; b++) {
        double refc[16], refi[16];
        compose_proj(proj + (size_t)(b*VV + 0)*2*16, refc);
        inv4(refc, refi);
        for (int v = 1; v < VV; v++) {
            double srcc[16], P[16];
            compose_proj(proj + (size_t)(b*VV + v)*2*16, srcc);
            mat4_mul(srcc, refi, P);
            float* dst = g_proj + ((v-1)*BB + b)*12;
            for (int r = 0; r < 3; r++)
                for (int c = 0; c < 3; c++) dst[r*3+c] = (float)P[r*4+c];
            dst[9]  = (float)P[0*4+3];
            dst[10] = (float)P[1*4+3];
            dst[11] = (float)P[2*4+3];
        }
    }
    // fold BN into MLP weights
    for (int o = 0; o < 16; o++) {
        double s = (double)g0[o] / sqrt((double)v0[o] + 1e-5);
        g_mlp[o]      = (float)((double)w0[o] * s);
        g_mlp[16 + o] = (float)((double)b0[o] - (double)m0[o] * s);
    }
    for (int j = 0; j < 8; j++) {
        double s = (double)g1[j] / sqrt((double)v1[j] + 1e-5);
        for (int o = 0; o < 16; o++)
            g_mlp[32 + j*16 + o] = (float)((double)w1[j*16+o] * s);
        g_mlp[160 + j] = (float)((double)b1[j] - (double)m1[j] * s);
        g_mlp[168 + j] = w2[j];
    }
    g_mlp[176] = b2[0];
    for (int k = 0; k < 27; k++) g_reg[k] = reg_w[k];
    g_reg[27] = reg_b[0];
}

// ======================= feature transpose to [b][v][h][w][c] =======================
__global__ void transpose_kernel(const float* __restrict__ feat) {
    int idx = blockIdx.x * blockDim.x + threadIdx.x;   // over B*V*H*W
    if (idx >= BB*VV*HWW) return;
    int p  = idx % HWW;
    int bv = idx / HWW;
    const float* src = feat + (size_t)bv * CC * HWW + p;
    float v[CC];
#pragma unroll
    for (int c = 0; c < CC; c++) v[c] = src[(size_t)c * HWW];
    float4* dst = (float4*)(g_feat_t + ((size_t)bv * HWW + p) * CC);
    dst[0] = make_float4(v[0],  v[1],  v[2],  v[3]);
    dst[1] = make_float4(v[4],  v[5],  v[6],  v[7]);
    dst[2] = make_float4(v[8],  v[9],  v[10], v[11]);
    dst[3] = make_float4(v[12], v[13], v[14], v[15]);
}

// ======================= warp + sim + pixelwise-net (per view) =======================
__global__ void sim_vw_kernel(const float* __restrict__ depth_values, float* __restrict__ out) {
    __shared__ float s_mlp[177];
    for (int i = threadIdx.x; i < 177; i += blockDim.x) s_mlp[i] = g_mlp[i];
    __syncthreads();

    int idx = blockIdx.x * blockDim.x + threadIdx.x;   // over NV*NPIX
    if (idx >= NV * NPIX) return;
    int view = 1 + idx / NPIX;
    int pid  = idx % NPIX;
    int b = pid / HWW;
    int p = pid - b * HWW;
    int h = p / WW;
    int w = p - h * WW;

    // ref feature vector (view 0), C=16 floats
    const float4* rf = (const float4*)(g_feat_t + ((size_t)(b*VV + 0) * HWW + p) * CC);
    float4 r0 = rf[0], r1 = rf[1], r2 = rf[2], r3 = rf[3];

    const float* pr = g_proj + ((view-1)*BB + b) * 12;
    float fw = (float)w, fh = (float)h;
    float rx = pr[0]*fw + pr[1]*fh + pr[2];
    float ry = pr[3]*fw + pr[4]*fh + pr[5];
    float rz = pr[6]*fw + pr[7]*fh + pr[8];
    float tx = pr[9], ty = pr[10], tz = pr[11];

    const float* src = g_feat_t + (size_t)(b*VV + view) * HWW * CC;
    const float* dv  = depth_values + (size_t)b * DD * HWW + p;
    float* simout    = g_sim + (size_t)(view-1) * BDHW + (size_t)b * DD * HWW + p;

    float omax = -3.4e38f;

    for (int d = 0; d < DD; d++) {
        float dep = dv[(size_t)d * HWW];
        float X = fmaf(rx, dep, tx);
        float Y = fmaf(ry, dep, ty);
        float Z = fmaf(rz, dep, tz);
        float px = X / Z;
        float py = Y / Z;
        float x0f = floorf(px), y0f = floorf(py);
        float fx = px - x0f, fy = py - y0f;

        bool vx0 = (x0f >= 0.f)       && (x0f <= (float)(WW-1));
        bool vx1 = (x0f + 1.f >= 0.f) && (x0f + 1.f <= (float)(WW-1));
        bool vy0 = (y0f >= 0.f)       && (y0f <= (float)(HH-1));
        bool vy1 = (y0f + 1.f >= 0.f) && (y0f + 1.f <= (float)(HH-1));

        int ix0 = (int)fminf(fmaxf(x0f,       0.f), (float)(WW-1));
        int ix1 = (int)fminf(fmaxf(x0f + 1.f, 0.f), (float)(WW-1));
        int iy0 = (int)fminf(fmaxf(y0f,       0.f), (float)(HH-1));
        int iy1 = (int)fminf(fmaxf(y0f + 1.f, 0.f), (float)(HH-1));

        float w00 = (1.f - fx) * (1.f - fy);
        float w10 = fx * (1.f - fy);
        float w01 = (1.f - fx) * fy;
        float w11 = fx * fy;

        float sim = 0.f;
#define CORNER_DOT(XI, YI) ({                                                   \
            const float4* f = (const float4*)(src + ((size_t)(YI)*WW + (XI)) * CC); \
            float4 a = f[0], bq = f[1], cq = f[2], dq = f[3];                   \
            a.x*r0.x + a.y*r0.y + a.z*r0.z + a.w*r0.w +                         \
            bq.x*r1.x + bq.y*r1.y + bq.z*r1.z + bq.w*r1.w +                     \
            cq.x*r2.x + cq.y*r2.y + cq.z*r2.z + cq.w*r2.w +                     \
            dq.x*r3.x + dq.y*r3.y + dq.z*r3.z + dq.w*r3.w; })

        if (vx0 && vy0 && w00 != 0.f) sim = fmaf(w00, CORNER_DOT(ix0, iy0), sim);
        if (vx0 && vy1 && w01 != 0.f) sim = fmaf(w01, CORNER_DOT(ix0, iy1), sim);
        if (vx1 && vy0 && w10 != 0.f) sim = fmaf(w10, CORNER_DOT(ix1, iy0), sim);
        if (vx1 && vy1 && w11 != 0.f) sim = fmaf(w11, CORNER_DOT(ix1, iy1), sim);
#undef CORNER_DOT
        sim *= 0.0625f;   // mean over C=16
        simout[(size_t)d * HWW] = sim;

        // pixelwise MLP (BN folded): 1 -> 16 -> 8 -> 1
        float a1[8];
#pragma unroll
        for (int j = 0; j < 8; j++) a1[j] = s_mlp[160 + j];
#pragma unroll
        for (int o = 0; o < 16; o++) {
            float h0 = fmaxf(0.f, fmaf(s_mlp[o], sim, s_mlp[16 + o]));
#pragma unroll
            for (int j = 0; j < 8; j++) a1[j] = fmaf(s_mlp[32 + j*16 + o], h0, a1[j]);
        }
        float ov = s_mlp[176];
#pragma unroll
        for (int j = 0; j < 8; j++) ov = fmaf(s_mlp[168 + j], fmaxf(0.f, a1[j]), ov);
        omax = fmaxf(omax, ov);
    }

    // sigmoid monotone: max over d of sigmoid == sigmoid of max
    float vw = 1.f / (1.f + expf(-omax));
    g_vw[(size_t)(view-1) * NPIX + pid] = vw;
    out[OFF_VW + (size_t)b * NV * HWW + (size_t)(view-1) * HWW + p] = vw;
}

// ======================= weighted combine =======================
__global__ void combine_kernel() {
    int idx = blockIdx.x * blockDim.x + threadIdx.x;   // over BDHW
    if (idx >= BDHW) return;
    int b = idx / (DD * HWW);
    int p = idx % HWW;
    float w0v = g_vw[(size_t)b * HWW + p];
    float w1v = g_vw[(size_t)NPIX + (size_t)b * HWW + p];
    float s0 = g_sim[idx];
    float s1 = g_sim[(size_t)BDHW + idx];
    g_simil[idx] = (s0 * w0v + s1 * w1v) / (1e-5f + w0v + w1v);
}

// ======================= 3x3x3 conv (SAME, zero pad) =======================
__global__ void conv_kernel() {
    int idx = blockIdx.x * blockDim.x + threadIdx.x;   // over BDHW
    if (idx >= BDHW) return;
    int p = idx % HWW;
    int d = (idx / HWW) % DD;
    int b = idx / (DD * HWW);
    int h = p / WW;
    int w = p - h * WW;
    float acc = g_reg[27];
#pragma unroll
    for (int dz = 0; dz < 3; dz++) {
        int dd = d + dz - 1;
        if ((unsigned)dd >= DD) continue;
#pragma unroll
        for (int dy = 0; dy < 3; dy++) {
            int hh = h + dy - 1;
            if ((unsigned)hh >= HH) continue;
#pragma unroll
            for (int dx = 0; dx < 3; dx++) {
                int wwp = w + dx - 1;
                if ((unsigned)wwp >= WW) continue;
                acc = fmaf(g_reg[(dz*3 + dy)*3 + dx],
                           g_simil[((size_t)(b*DD + dd) * HH + hh) * WW + wwp], acc);
            }
        }
    }
    g_cost[idx] = acc;
}

// ======================= softmax + argmax + outputs =======================
__global__ void softmax_kernel(const float* __restrict__ depth_values, float* __restrict__ out) {
    int idx = blockIdx.x * blockDim.x + threadIdx.x;   // over NPIX
    if (idx >= NPIX) return;
    int b = idx / HWW;
    int p = idx - b * HWW;
    const float* cp = g_cost + (size_t)b * DD * HWW + p;
    float c[DD];
#pragma unroll
    for (int d = 0; d < DD; d++) c[d] = cp[(size_t)d * HWW];
    float m = c[0];
    int am = 0;
#pragma unroll
    for (int d = 1; d < DD; d++) {
        if (c[d] > m) { m = c[d]; am = d; }
    }
    float sum = 0.f;
#pragma unroll
    for (int d = 0; d < DD; d++) sum += expf(c[d] - m);
    float inv = 1.f / sum;
    float* pp = out + OFF_PROB + (size_t)b * DD * HWW + p;
#pragma unroll
    for (int d = 0; d < DD; d++) pp[(size_t)d * HWW] = expf(c[d] - m) * inv;
    out[OFF_DEPTH + idx] = depth_values[(size_t)b * DD * HWW + (size_t)am * HWW + p];
    out[OFF_CONF + idx] = inv;   // prob at argmax = exp(0)/sum
}

// ======================= launch =======================
extern "C" void kernel_launch(void* const* d_in, const int* in_sizes, int n_in,
                              void* d_out, int out_size) {
    const float* features     = (const float*)d_in[0];
    const float* proj         = (const float*)d_in[1];
    const float* depth_values = (const float*)d_in[2];
    const float* w0 = (const float*)d_in[3];
    const float* g0 = (const float*)d_in[4];
    const float* b0 = (const float*)d_in[5];
    const float* m0 = (const float*)d_in[6];
    const float* v0 = (const float*)d_in[7];
    const float* w1 = (const float*)d_in[8];
    const float* g1 = (const float*)d_in[9];
    const float* b1 = (const float*)d_in[10];
    const float* m1 = (const float*)d_in[11];
    const float* v1 = (const float*)d_in[12];
    const float* w2 = (const float*)d_in[13];
    const float* b2 = (const float*)d_in[14];
    const float* reg_w = (const float*)d_in[15];
    const float* reg_b = (const float*)d_in[16];
    float* out = (float*)d_out;

    transpose_kernel<<<(BB*VV*HWW + 255) / 256, 256>>>(features);
    prep_kernel<<<1, 32>>>(proj, w0, g0, b0, m0, v0, w1, g1, b1, m1, v1, w2, b2, reg_w, reg_b);
    sim_vw_kernel<<<(NV*NPIX + 127) / 128, 128>>>(depth_values, out);
    combine_kernel<<<(BDHW + 255) / 256, 256>>>();
    conv_kernel<<<(BDHW + 255) / 256, 256>>>();
    softmax_kernel<<<(NPIX + 127) / 128, 128>>>(depth_values, out);
}

// round 3
// speedup vs baseline: 1.1973x; 1.1973x over previous
#include <cuda_runtime.h>
#include <math.h>

// Fixed problem shapes
#define BB 2
#define VV 3
#define CC 16
#define HH 128
#define WW 160
#define DD 48
#define HWW (HH*WW)            // 20480
#define NPIX (BB*HWW)          // 40960
#define BDHW (BB*DD*HWW)       // 1966080
#define NV (VV-1)              // 2 source views

// Output layout (concatenated float32 outputs in reference return order)
#define OFF_DEPTH 0
#define OFF_CONF  (NPIX)                   // 40960
#define OFF_PROB  (2*NPIX)                 // 81920
#define OFF_VW    (2*NPIX + BDHW)          // 2048000

// -------- scratch (device globals; no allocation allowed) --------
__device__ float g_feat_t[(size_t)BB*VV*HWW*CC];   // [b][v][h][w][c]
__device__ float g_sim[(size_t)NV*BDHW];           // [view][b][d][h][w]
__device__ float g_simil[BDHW];                    // combined similarity
__device__ float g_proj[NV*BB*12];                 // per (view,b): rot 9 + trans 3
__device__ float g_mlp[177];                       // fw0[16] fc0[16] fw1[128] fc1[8] fw2[8] fb2
__device__ float g_reg[28];                        // reg_w[27] + reg_b

// ======================= prep: matrices + weight folding =======================
__device__ void mat4_mul(const double* A, const double* B, double* Cm) {
    for (int r = 0; r < 4; r++)
        for (int c = 0; c < 4; c++) {
            double s = 0.0;
            for (int k = 0; k < 4; k++) s += A[r*4+k] * B[k*4+c];
            Cm[r*4+c] = s;
        }
}

__device__ void compose_proj(const float* p, double* out) {
    const float* E = p;
    const float* K = p + 16;
    for (int i = 0; i < 16; i++) out[i] = (double)E[i];
    for (int r = 0; r < 3; r++)
        for (int c = 0; c < 4; c++) {
            double s = 0.0;
            for (int k = 0; k < 3; k++) s += (double)K[r*4+k] * (double)E[k*4+c];
            out[r*4+c] = s;
        }
}

__device__ void inv4(const double* A, double* out) {
    double M[4][8];
    for (int i = 0; i < 4; i++)
        for (int j = 0; j < 4; j++) { M[i][j] = A[i*4+j]; M[i][4+j] = (i == j) ? 1.0 : 0.0; }
    for (int col = 0; col < 4; col++) {
        int piv = col;
        for (int r = col + 1; r < 4; r++)
            if (fabs(M[r][col]) > fabs(M[piv][col])) piv = r;
        if (piv != col)
            for (int j = 0; j < 8; j++) { double t = M[col][j]; M[col][j] = M[piv][j]; M[piv][j] = t; }
        double pv = M[col][col];
        for (int j = 0; j < 8; j++) M[col][j] /= pv;
        for (int r = 0; r < 4; r++) {
            if (r == col) continue;
            double f = M[r][col];
            for (int j = 0; j < 8; j++) M[r][j] -= f * M[col][j];
        }
    }
    for (int i = 0; i < 4; i++)
        for (int j = 0; j < 4; j++) out[i*4+j] = M[i][4+j];
}

__global__ void prep_kernel(const float* proj,
                            const float* w0, const float* g0, const float* b0,
                            const float* m0, const float* v0,
                            const float* w1, const float* g1, const float* b1,
                            const float* m1, const float* v1,
                            const float* w2, const float* b2,
                            const float* reg_w, const float* reg_b) {
    if (blockIdx.x != 0 || threadIdx.x != 0) return;
    for (int b = 0; b < BB; b++) {
        double refc[16], refi[16];
        compose_proj(proj + (size_t)(b*VV + 0)*2*16, refc);
        inv4(refc, refi);
        for (int v = 1; v < VV; v++) {
            double srcc[16], P[16];
            compose_proj(proj + (size_t)(b*VV + v)*2*16, srcc);
            mat4_mul(srcc, refi, P);
            float* dst = g_proj + ((v-1)*BB + b)*12;
            for (int r = 0; r < 3; r++)
                for (int c = 0; c < 3; c++) dst[r*3+c] = (float)P[r*4+c];
            dst[9]  = (float)P[0*4+3];
            dst[10] = (float)P[1*4+3];
            dst[11] = (float)P[2*4+3];
        }
    }
    for (int o = 0; o < 16; o++) {
        double s = (double)g0[o] / sqrt((double)v0[o] + 1e-5);
        g_mlp[o]      = (float)((double)w0[o] * s);
        g_mlp[16 + o] = (float)((double)b0[o] - (double)m0[o] * s);
    }
    for (int j = 0; j < 8; j++) {
        double s = (double)g1[j] / sqrt((double)v1[j] + 1e-5);
        for (int o = 0; o < 16; o++)
            g_mlp[32 + j*16 + o] = (float)((double)w1[j*16+o] * s);
        g_mlp[160 + j] = (float)((double)b1[j] - (double)m1[j] * s);
        g_mlp[168 + j] = w2[j];
    }
    g_mlp[176] = b2[0];
    for (int k = 0; k < 27; k++) g_reg[k] = reg_w[k];
    g_reg[27] = reg_b[0];
}

// ======================= feature transpose to [b][v][h][w][c] =======================
__global__ void transpose_kernel(const float* __restrict__ feat) {
    int idx = blockIdx.x * blockDim.x + threadIdx.x;   // over B*V*H*W
    if (idx >= BB*VV*HWW) return;
    int p  = idx % HWW;
    int bv = idx / HWW;
    const float* src = feat + (size_t)bv * CC * HWW + p;
    float v[CC];
#pragma unroll
    for (int c = 0; c < CC; c++) v[c] = src[(size_t)c * HWW];
    float4* dst = (float4*)(g_feat_t + ((size_t)bv * HWW + p) * CC);
    dst[0] = make_float4(v[0],  v[1],  v[2],  v[3]);
    dst[1] = make_float4(v[4],  v[5],  v[6],  v[7]);
    dst[2] = make_float4(v[8],  v[9],  v[10], v[11]);
    dst[3] = make_float4(v[12], v[13], v[14], v[15]);
}

// ======================= gather: warped similarity (channel-split, 4 lanes/pixel) =======================
// thread = (view,pixel, q) where q in [0,4) indexes float4 quarters of the C=16 vector.
__global__ void gather_kernel(const float* __restrict__ depth_values) {
    int tid = blockIdx.x * blockDim.x + threadIdx.x;   // over NV*NPIX*4 (exact multiple of 128)
    int q  = tid & 3;
    int vp = tid >> 2;
    int view = 1 + vp / NPIX;
    int pid  = vp % NPIX;
    int b = pid / HWW;
    int p = pid - b * HWW;
    int h = p / WW;
    int w = p - h * WW;

    // this lane's quarter of the ref feature vector
    float4 rq = ((const float4*)(g_feat_t + ((size_t)(b*VV + 0) * HWW + p) * CC))[q];

    const float* pr = g_proj + ((view-1)*BB + b) * 12;
    float fw = (float)w, fh = (float)h;
    float rx = pr[0]*fw + pr[1]*fh + pr[2];
    float ry = pr[3]*fw + pr[4]*fh + pr[5];
    float rz = pr[6]*fw + pr[7]*fh + pr[8];
    float tx = pr[9], ty = pr[10], tz = pr[11];

    const float* src = g_feat_t + (size_t)(b*VV + view) * HWW * CC;
    const float* dv  = depth_values + (size_t)b * DD * HWW + p;
    float* simout    = g_sim + (size_t)(view-1) * BDHW + (size_t)b * DD * HWW + p;

    for (int d = 0; d < DD; d++) {
        float dep = __ldg(dv + (size_t)d * HWW);
        float X = fmaf(rx, dep, tx);
        float Y = fmaf(ry, dep, ty);
        float Z = fmaf(rz, dep, tz);
        float px = X / Z;            // exact IEEE division (argmax-sensitive)
        float py = Y / Z;
        float x0f = floorf(px), y0f = floorf(py);
        float fx = px - x0f, fy = py - y0f;

        float vx0 = (x0f >= 0.f       && x0f       <= (float)(WW-1)) ? 1.f : 0.f;
        float vx1 = (x0f + 1.f >= 0.f && x0f + 1.f <= (float)(WW-1)) ? 1.f : 0.f;
        float vy0 = (y0f >= 0.f       && y0f       <= (float)(HH-1)) ? 1.f : 0.f;
        float vy1 = (y0f + 1.f >= 0.f && y0f + 1.f <= (float)(HH-1)) ? 1.f : 0.f;

        int ix0 = (int)fminf(fmaxf(x0f,       0.f), (float)(WW-1));
        int ix1 = (int)fminf(fmaxf(x0f + 1.f, 0.f), (float)(WW-1));
        int iy0 = (int)fminf(fmaxf(y0f,       0.f), (float)(HH-1));
        int iy1 = (int)fminf(fmaxf(y0f + 1.f, 0.f), (float)(HH-1));

        float w00 = (1.f - fx) * (1.f - fy) * (vx0 * vy0);
        float w10 = fx * (1.f - fy) * (vx1 * vy0);
        float w01 = (1.f - fx) * fy * (vx0 * vy1);
        float w11 = fx * fy * (vx1 * vy1);

        const float4 f00 = ((const float4*)(src + ((size_t)(iy0*WW + ix0)) * CC))[q];
        const float4 f10 = ((const float4*)(src + ((size_t)(iy0*WW + ix1)) * CC))[q];
        const float4 f01 = ((const float4*)(src + ((size_t)(iy1*WW + ix0)) * CC))[q];
        const float4 f11 = ((const float4*)(src + ((size_t)(iy1*WW + ix1)) * CC))[q];

        float d00 = fmaf(f00.x, rq.x, fmaf(f00.y, rq.y, fmaf(f00.z, rq.z, f00.w * rq.w)));
        float d10 = fmaf(f10.x, rq.x, fmaf(f10.y, rq.y, fmaf(f10.z, rq.z, f10.w * rq.w)));
        float d01 = fmaf(f01.x, rq.x, fmaf(f01.y, rq.y, fmaf(f01.z, rq.z, f01.w * rq.w)));
        float d11 = fmaf(f11.x, rq.x, fmaf(f11.y, rq.y, fmaf(f11.z, rq.z, f11.w * rq.w)));

        float part = fmaf(w00, d00, fmaf(w10, d10, fmaf(w01, d01, w11 * d11)));
        part += __shfl_xor_sync(0xffffffffu, part, 1);
        part += __shfl_xor_sync(0xffffffffu, part, 2);
        if (q == 0) simout[(size_t)d * HWW] = part * 0.0625f;
    }
}

// ======================= pixelwise MLP (both views) + combine =======================
__global__ void vw_combine_kernel(float* __restrict__ out) {
    __shared__ float s_mlp[177];
    for (int i = threadIdx.x; i < 177; i += blockDim.x) s_mlp[i] = g_mlp[i];
    __syncthreads();

    int pid = blockIdx.x * blockDim.x + threadIdx.x;
    if (pid >= NPIX) return;
    int b = pid / HWW;
    int p = pid - b * HWW;
    const float* sp0 = g_sim + (size_t)b * DD * HWW + p;
    const float* sp1 = g_sim + (size_t)BDHW + (size_t)b * DD * HWW + p;

    float omax0 = -3.4e38f, omax1 = -3.4e38f;
    for (int d = 0; d < DD; d++) {
        float sa = sp0[(size_t)d * HWW];
        float sb = sp1[(size_t)d * HWW];
        float a1a[8], a1b[8];
#pragma unroll
        for (int j = 0; j < 8; j++) { a1a[j] = s_mlp[160 + j]; a1b[j] = a1a[j]; }
#pragma unroll
        for (int o = 0; o < 16; o++) {
            float wo = s_mlp[o], co = s_mlp[16 + o];
            float ha = fmaxf(0.f, fmaf(wo, sa, co));
            float hb = fmaxf(0.f, fmaf(wo, sb, co));
#pragma unroll
            for (int j = 0; j < 8; j++) {
                float wj = s_mlp[32 + j*16 + o];
                a1a[j] = fmaf(wj, ha, a1a[j]);
                a1b[j] = fmaf(wj, hb, a1b[j]);
            }
        }
        float ova = s_mlp[176], ovb = ova;
#pragma unroll
        for (int j = 0; j < 8; j++) {
            float wj = s_mlp[168 + j];
            ova = fmaf(wj, fmaxf(0.f, a1a[j]), ova);
            ovb = fmaf(wj, fmaxf(0.f, a1b[j]), ovb);
        }
        omax0 = fmaxf(omax0, ova);
        omax1 = fmaxf(omax1, ovb);
    }

    // exact sigmoid (feeds cost -> argmax)
    float vw0 = 1.f / (1.f + expf(-omax0));
    float vw1 = 1.f / (1.f + expf(-omax1));
    out[OFF_VW + (size_t)b * NV * HWW + p] = vw0;
    out[OFF_VW + (size_t)b * NV * HWW + HWW + p] = vw1;

    float denom = 1e-5f + vw0 + vw1;
    float* so = g_simil + (size_t)b * DD * HWW + p;
    for (int d = 0; d < DD; d++) {
        float sa = sp0[(size_t)d * HWW];
        float sb = sp1[(size_t)d * HWW];
        so[(size_t)d * HWW] = (sa * vw0 + sb * vw1) / denom;   // exact division
    }
}

// ======================= fused 3x3x3 conv + softmax + argmax + outputs =======================
__global__ void conv_softmax_kernel(const float* __restrict__ depth_values, float* __restrict__ out) {
    __shared__ float s_k[28];
    if (threadIdx.x < 28) s_k[threadIdx.x] = g_reg[threadIdx.x];
    __syncthreads();

    int pid = blockIdx.x * blockDim.x + threadIdx.x;
    if (pid >= NPIX) return;
    int b = pid / HWW;
    int p = pid - b * HWW;
    int h = p / WW;
    int w = p - h * WW;

    float c[DD];
    float bias = s_k[27];
#pragma unroll
    for (int d = 0; d < DD; d++) c[d] = bias;

    bool wl = (w > 0), wr = (w < WW - 1);
#pragma unroll
    for (int dp = 0; dp < DD; dp++) {
        const float* base = g_simil + (size_t)(b*DD + dp) * HWW;
        float n[9];
#pragma unroll
        for (int dy = 0; dy < 3; dy++) {
            int hh = h + dy - 1;
            bool vy = (unsigned)hh < (unsigned)HH;
            const float* rowp = base + hh * WW + w;
            n[dy*3+0] = (vy && wl) ? rowp[-1] : 0.f;
            n[dy*3+1] = vy ? rowp[0] : 0.f;
            n[dy*3+2] = (vy && wr) ? rowp[1] : 0.f;
        }
#pragma unroll
        for (int dz = 0; dz < 3; dz++) {
            int od = dp + 1 - dz;
            if (od < 0 || od >= DD) continue;
            float acc = 0.f;
#pragma unroll
            for (int i = 0; i < 9; i++) acc = fmaf(s_k[dz*9+i], n[i], acc);
            c[od] += acc;
        }
    }

    float m = c[0]; int am = 0;
#pragma unroll
    for (int d = 1; d < DD; d++) if (c[d] > m) { m = c[d]; am = d; }
    float sum = 0.f;
#pragma unroll
    for (int d = 0; d < DD; d++) { float e = __expf(c[d] - m); c[d] = e; sum += e; }
    float inv = __fdividef(1.f, sum);
    float* pp = out + OFF_PROB + (size_t)b * DD * HWW + p;
#pragma unroll
    for (int d = 0; d < DD; d++) pp[(size_t)d * HWW] = c[d] * inv;
    out[OFF_DEPTH + pid] = depth_values[(size_t)b * DD * HWW + (size_t)am * HWW + p];
    out[OFF_CONF + pid] = inv;
}

// ======================= launch =======================
extern "C" void kernel_launch(void* const* d_in, const int* in_sizes, int n_in,
                              void* d_out, int out_size) {
    const float* features     = (const float*)d_in[0];
    const float* proj         = (const float*)d_in[1];
    const float* depth_values = (const float*)d_in[2];
    const float* w0 = (const float*)d_in[3];
    const float* g0 = (const float*)d_in[4];
    const float* b0 = (const float*)d_in[5];
    const float* m0 = (const float*)d_in[6];
    const float* v0 = (const float*)d_in[7];
    const float* w1 = (const float*)d_in[8];
    const float* g1 = (const float*)d_in[9];
    const float* b1 = (const float*)d_in[10];
    const float* m1 = (const float*)d_in[11];
    const float* v1 = (const float*)d_in[12];
    const float* w2 = (const float*)d_in[13];
    const float* b2 = (const float*)d_in[14];
    const float* reg_w = (const float*)d_in[15];
    const float* reg_b = (const float*)d_in[16];
    float* out = (float*)d_out;

    transpose_kernel<<<(BB*VV*HWW + 255) / 256, 256>>>(features);
    prep_kernel<<<1, 32>>>(proj, w0, g0, b0, m0, v0, w1, g1, b1, m1, v1, w2, b2, reg_w, reg_b);
    gather_kernel<<<(NV*NPIX*4) / 128, 128>>>(depth_values);
    vw_combine_kernel<<<(NPIX + 127) / 128, 128>>>(out);
    conv_softmax_kernel<<<(NPIX + 127) / 128, 128>>>(depth_values, out);
}

// round 4
// speedup vs baseline: 1.3066x; 1.0912x over previous
#include <cuda_runtime.h>
#include <math.h>

// Fixed problem shapes
#define BB 2
#define VV 3
#define CC 16
#define HH 128
#define WW 160
#define DD 48
#define HWW (HH*WW)            // 20480
#define NPIX (BB*HWW)          // 40960
#define BDHW (BB*DD*HWW)       // 1966080
#define NV (VV-1)              // 2 source views

// Output layout
#define OFF_DEPTH 0
#define OFF_CONF  (NPIX)
#define OFF_PROB  (2*NPIX)
#define OFF_VW    (2*NPIX + BDHW)

// -------- scratch --------
__device__ float g_feat_t[(size_t)BB*VV*HWW*CC];   // [b][v][h][w][c]
__device__ float g_sim[(size_t)NV*BDHW];           // [view][b][d][h][w]
__device__ float g_vw[(size_t)NV*NPIX];            // [view][b][h][w]
__device__ float g_simil[BDHW];
__device__ float g_proj[NV*BB*12];
__device__ float g_mlp[177];
__device__ float g_reg[28];

// ======================= prep =======================
__device__ void mat4_mul(const double* A, const double* B, double* Cm) {
    for (int r = 0; r < 4; r++)
        for (int c = 0; c < 4; c++) {
            double s = 0.0;
            for (int k = 0; k < 4; k++) s += A[r*4+k] * B[k*4+c];
            Cm[r*4+c] = s;
        }
}

__device__ void compose_proj(const float* p, double* out) {
    const float* E = p;
    const float* K = p + 16;
    for (int i = 0; i < 16; i++) out[i] = (double)E[i];
    for (int r = 0; r < 3; r++)
        for (int c = 0; c < 4; c++) {
            double s = 0.0;
            for (int k = 0; k < 3; k++) s += (double)K[r*4+k] * (double)E[k*4+c];
            out[r*4+c] = s;
        }
}

__device__ void inv4(const double* A, double* out) {
    double M[4][8];
    for (int i = 0; i < 4; i++)
        for (int j = 0; j < 4; j++) { M[i][j] = A[i*4+j]; M[i][4+j] = (i == j) ? 1.0 : 0.0; }
    for (int col = 0; col < 4; col++) {
        int piv = col;
        for (int r = col + 1; r < 4; r++)
            if (fabs(M[r][col]) > fabs(M[piv][col])) piv = r;
        if (piv != col)
            for (int j = 0; j < 8; j++) { double t = M[col][j]; M[col][j] = M[piv][j]; M[piv][j] = t; }
        double pv = M[col][col];
        for (int j = 0; j < 8; j++) M[col][j] /= pv;
        for (int r = 0; r < 4; r++) {
            if (r == col) continue;
            double f = M[r][col];
            for (int j = 0; j < 8; j++) M[r][j] -= f * M[col][j];
        }
    }
    for (int i = 0; i < 4; i++)
        for (int j = 0; j < 4; j++) out[i*4+j] = M[i][4+j];
}

__global__ void prep_kernel(const float* proj,
                            const float* w0, const float* g0, const float* b0,
                            const float* m0, const float* v0,
                            const float* w1, const float* g1, const float* b1,
                            const float* m1, const float* v1,
                            const float* w2, const float* b2,
                            const float* reg_w, const float* reg_b) {
    if (blockIdx.x != 0 || threadIdx.x != 0) return;
    for (int b = 0; b < BB; b++) {
        double refc[16], refi[16];
        compose_proj(proj + (size_t)(b*VV + 0)*2*16, refc);
        inv4(refc, refi);
        for (int v = 1; v < VV; v++) {
            double srcc[16], P[16];
            compose_proj(proj + (size_t)(b*VV + v)*2*16, srcc);
            mat4_mul(srcc, refi, P);
            float* dst = g_proj + ((v-1)*BB + b)*12;
            for (int r = 0; r < 3; r++)
                for (int c = 0; c < 3; c++) dst[r*3+c] = (float)P[r*4+c];
            dst[9]  = (float)P[0*4+3];
            dst[10] = (float)P[1*4+3];
            dst[11] = (float)P[2*4+3];
        }
    }
    for (int o = 0; o < 16; o++) {
        double s = (double)g0[o] / sqrt((double)v0[o] + 1e-5);
        g_mlp[o]      = (float)((double)w0[o] * s);
        g_mlp[16 + o] = (float)((double)b0[o] - (double)m0[o] * s);
    }
    for (int j = 0; j < 8; j++) {
        double s = (double)g1[j] / sqrt((double)v1[j] + 1e-5);
        for (int o = 0; o < 16; o++)
            g_mlp[32 + j*16 + o] = (float)((double)w1[j*16+o] * s);
        g_mlp[160 + j] = (float)((double)b1[j] - (double)m1[j] * s);
        g_mlp[168 + j] = w2[j];
    }
    g_mlp[176] = b2[0];
    for (int k = 0; k < 27; k++) g_reg[k] = reg_w[k];
    g_reg[27] = reg_b[0];
}

// ======================= feature transpose to [b][v][h][w][c] =======================
__global__ void transpose_kernel(const float* __restrict__ feat) {
    int idx = blockIdx.x * blockDim.x + threadIdx.x;
    if (idx >= BB*VV*HWW) return;
    int p  = idx % HWW;
    int bv = idx / HWW;
    const float* src = feat + (size_t)bv * CC * HWW + p;
    float v[CC];
#pragma unroll
    for (int c = 0; c < CC; c++) v[c] = src[(size_t)c * HWW];
    float4* dst = (float4*)(g_feat_t + ((size_t)bv * HWW + p) * CC);
    dst[0] = make_float4(v[0],  v[1],  v[2],  v[3]);
    dst[1] = make_float4(v[4],  v[5],  v[6],  v[7]);
    dst[2] = make_float4(v[8],  v[9],  v[10], v[11]);
    dst[3] = make_float4(v[12], v[13], v[14], v[15]);
}

// ======================= fused gather + sim + MLP =======================
// thread = (view, pixel, q), q in [0,4): float4 quarter of C=16 vector.
// Corner features cached in registers across the depth sweep (reload only when
// the integer corner changes -- with these cameras, essentially never).
// Depths processed in blocks of 4; lane q keeps sim for depth base+q, and the
// MLP runs once per block with all 4 lanes active on distinct depths.
__global__ void gather_mlp_kernel(const float* __restrict__ depth_values,
                                  float* __restrict__ out) {
    __shared__ float s_mlp[177];
    for (int i = threadIdx.x; i < 177; i += blockDim.x) s_mlp[i] = g_mlp[i];
    __syncthreads();

    int tid = blockIdx.x * blockDim.x + threadIdx.x;   // NV*NPIX*4, multiple of 128
    int q  = tid & 3;
    int vp = tid >> 2;
    int view = 1 + vp / NPIX;
    int pid  = vp % NPIX;
    int b = pid / HWW;
    int p = pid - b * HWW;
    int h = p / WW;
    int w = p - h * WW;

    float4 rq = ((const float4*)(g_feat_t + ((size_t)(b*VV + 0) * HWW + p) * CC))[q];

    const float* pr = g_proj + ((view-1)*BB + b) * 12;
    float fw = (float)w, fh = (float)h;
    float rx = pr[0]*fw + pr[1]*fh + pr[2];
    float ry = pr[3]*fw + pr[4]*fh + pr[5];
    float rz = pr[6]*fw + pr[7]*fh + pr[8];
    float tx = pr[9], ty = pr[10], tz = pr[11];

    const float* src = g_feat_t + (size_t)(b*VV + view) * HWW * CC;
    const float* dv  = depth_values + (size_t)b * DD * HWW + p;
    float* simout    = g_sim + (size_t)(view-1) * BDHW + (size_t)b * DD * HWW + p;

    // cached corners
    int cix0 = -100000, ciy0 = -100000;
    float4 f00, f10, f01, f11;
    f00 = f10 = f01 = f11 = make_float4(0.f, 0.f, 0.f, 0.f);

    float omax = -3.4e38f;

    for (int base = 0; base < DD; base += 4) {
        float mysim = 0.f;
#pragma unroll
        for (int j = 0; j < 4; j++) {
            int d = base + j;
            float dep = __ldg(dv + (size_t)d * HWW);
            float X = fmaf(rx, dep, tx);
            float Y = fmaf(ry, dep, ty);
            float Z = fmaf(rz, dep, tz);
            float px = X / Z;            // exact IEEE division (argmax-sensitive)
            float py = Y / Z;
            float x0f = floorf(px), y0f = floorf(py);
            float fx = px - x0f, fy = py - y0f;

            float vx0 = (x0f >= 0.f       && x0f       <= (float)(WW-1)) ? 1.f : 0.f;
            float vx1 = (x0f + 1.f >= 0.f && x0f + 1.f <= (float)(WW-1)) ? 1.f : 0.f;
            float vy0 = (y0f >= 0.f       && y0f       <= (float)(HH-1)) ? 1.f : 0.f;
            float vy1 = (y0f + 1.f >= 0.f && y0f + 1.f <= (float)(HH-1)) ? 1.f : 0.f;

            int ix0 = (int)fminf(fmaxf(x0f,       0.f), (float)(WW-1));
            int ix1 = (int)fminf(fmaxf(x0f + 1.f, 0.f), (float)(WW-1));
            int iy0 = (int)fminf(fmaxf(y0f,       0.f), (float)(HH-1));
            int iy1 = (int)fminf(fmaxf(y0f + 1.f, 0.f), (float)(HH-1));

            if (ix0 != cix0 || iy0 != ciy0) {
                // reload corners (ix1/iy1 are functions of ix0/iy0 via clamping,
                // but clamp means ix1 may equal ix0; addresses recomputed anyway)
                f00 = ((const float4*)(src + ((size_t)(iy0*WW + ix0)) * CC))[q];
                f10 = ((const float4*)(src + ((size_t)(iy0*WW + ix1)) * CC))[q];
                f01 = ((const float4*)(src + ((size_t)(iy1*WW + ix0)) * CC))[q];
                f11 = ((const float4*)(src + ((size_t)(iy1*WW + ix1)) * CC))[q];
                cix0 = ix0; ciy0 = iy0;
            }

            float w00 = (1.f - fx) * (1.f - fy) * (vx0 * vy0);
            float w10 = fx * (1.f - fy) * (vx1 * vy0);
            float w01 = (1.f - fx) * fy * (vx0 * vy1);
            float w11 = fx * fy * (vx1 * vy1);

            float d00 = fmaf(f00.x, rq.x, fmaf(f00.y, rq.y, fmaf(f00.z, rq.z, f00.w * rq.w)));
            float d10 = fmaf(f10.x, rq.x, fmaf(f10.y, rq.y, fmaf(f10.z, rq.z, f10.w * rq.w)));
            float d01 = fmaf(f01.x, rq.x, fmaf(f01.y, rq.y, fmaf(f01.z, rq.z, f01.w * rq.w)));
            float d11 = fmaf(f11.x, rq.x, fmaf(f11.y, rq.y, fmaf(f11.z, rq.z, f11.w * rq.w)));

            float part = fmaf(w00, d00, fmaf(w10, d10, fmaf(w01, d01, w11 * d11)));
            part += __shfl_xor_sync(0xffffffffu, part, 1);
            part += __shfl_xor_sync(0xffffffffu, part, 2);
            float sim = part * 0.0625f;
            if (q == 0) simout[(size_t)d * HWW] = sim;
            if (q == j) mysim = sim;       // lane q owns depth base+q
        }

        // MLP on mysim (all lanes active, each on its own depth)
        float a1[8];
#pragma unroll
        for (int j = 0; j < 8; j++) a1[j] = s_mlp[160 + j];
#pragma unroll
        for (int o = 0; o < 16; o++) {
            float h0 = fmaxf(0.f, fmaf(s_mlp[o], mysim, s_mlp[16 + o]));
#pragma unroll
            for (int j = 0; j < 8; j++) a1[j] = fmaf(s_mlp[32 + j*16 + o], h0, a1[j]);
        }
        float ov = s_mlp[176];
#pragma unroll
        for (int j = 0; j < 8; j++) ov = fmaf(s_mlp[168 + j], fmaxf(0.f, a1[j]), ov);
        omax = fmaxf(omax, ov);
    }

    // max over the 4 q-lanes
    omax = fmaxf(omax, __shfl_xor_sync(0xffffffffu, omax, 1));
    omax = fmaxf(omax, __shfl_xor_sync(0xffffffffu, omax, 2));

    if (q == 0) {
        float vw = 1.f / (1.f + expf(-omax));    // exact sigmoid
        g_vw[(size_t)(view-1) * NPIX + pid] = vw;
        out[OFF_VW + (size_t)b * NV * HWW + (size_t)(view-1) * HWW + p] = vw;
    }
}

// ======================= weighted combine =======================
__global__ void combine_kernel() {
    int idx = blockIdx.x * blockDim.x + threadIdx.x;   // over BDHW
    if (idx >= BDHW) return;
    int b = idx / (DD * HWW);
    int p = idx % HWW;
    float w0v = g_vw[(size_t)b * HWW + p];
    float w1v = g_vw[(size_t)NPIX + (size_t)b * HWW + p];
    float s0 = g_sim[idx];
    float s1 = g_sim[(size_t)BDHW + idx];
    g_simil[idx] = (s0 * w0v + s1 * w1v) / (1e-5f + w0v + w1v);   // exact division
}

// ======================= fused 3x3x3 conv + softmax + argmax + outputs =======================
__global__ void conv_softmax_kernel(const float* __restrict__ depth_values, float* __restrict__ out) {
    __shared__ float s_k[28];
    if (threadIdx.x < 28) s_k[threadIdx.x] = g_reg[threadIdx.x];
    __syncthreads();

    int pid = blockIdx.x * blockDim.x + threadIdx.x;
    if (pid >= NPIX) return;
    int b = pid / HWW;
    int p = pid - b * HWW;
    int h = p / WW;
    int w = p - h * WW;

    float c[DD];
    float bias = s_k[27];
#pragma unroll
    for (int d = 0; d < DD; d++) c[d] = bias;

    bool wl = (w > 0), wr = (w < WW - 1);
#pragma unroll
    for (int dp = 0; dp < DD; dp++) {
        const float* base = g_simil + (size_t)(b*DD + dp) * HWW;
        float n[9];
#pragma unroll
        for (int dy = 0; dy < 3; dy++) {
            int hh = h + dy - 1;
            bool vy = (unsigned)hh < (unsigned)HH;
            const float* rowp = base + hh * WW + w;
            n[dy*3+0] = (vy && wl) ? rowp[-1] : 0.f;
            n[dy*3+1] = vy ? rowp[0] : 0.f;
            n[dy*3+2] = (vy && wr) ? rowp[1] : 0.f;
        }
#pragma unroll
        for (int dz = 0; dz < 3; dz++) {
            int od = dp + 1 - dz;
            if (od < 0 || od >= DD) continue;
            float acc = 0.f;
#pragma unroll
            for (int i = 0; i < 9; i++) acc = fmaf(s_k[dz*9+i], n[i], acc);
            c[od] += acc;
        }
    }

    float m = c[0]; int am = 0;
#pragma unroll
    for (int d = 1; d < DD; d++) if (c[d] > m) { m = c[d]; am = d; }
    float sum = 0.f;
#pragma unroll
    for (int d = 0; d < DD; d++) { float e = __expf(c[d] - m); c[d] = e; sum += e; }
    float inv = __fdividef(1.f, sum);
    float* pp = out + OFF_PROB + (size_t)b * DD * HWW + p;
#pragma unroll
    for (int d = 0; d < DD; d++) pp[(size_t)d * HWW] = c[d] * inv;
    out[OFF_DEPTH + pid] = depth_values[(size_t)b * DD * HWW + (size_t)am * HWW + p];
    out[OFF_CONF + pid] = inv;
}

// ======================= launch =======================
extern "C" void kernel_launch(void* const* d_in, const int* in_sizes, int n_in,
                              void* d_out, int out_size) {
    const float* features     = (const float*)d_in[0];
    const float* proj         = (const float*)d_in[1];
    const float* depth_values = (const float*)d_in[2];
    const float* w0 = (const float*)d_in[3];
    const float* g0 = (const float*)d_in[4];
    const float* b0 = (const float*)d_in[5];
    const float* m0 = (const float*)d_in[6];
    const float* v0 = (const float*)d_in[7];
    const float* w1 = (const float*)d_in[8];
    const float* g1 = (const float*)d_in[9];
    const float* b1 = (const float*)d_in[10];
    const float* m1 = (const float*)d_in[11];
    const float* v1 = (const float*)d_in[12];
    const float* w2 = (const float*)d_in[13];
    const float* b2 = (const float*)d_in[14];
    const float* reg_w = (const float*)d_in[15];
    const float* reg_b = (const float*)d_in[16];
    float* out = (float*)d_out;

    transpose_kernel<<<(BB*VV*HWW + 255) / 256, 256>>>(features);
    prep_kernel<<<1, 32>>>(proj, w0, g0, b0, m0, v0, w1, g1, b1, m1, v1, w2, b2, reg_w, reg_b);
    gather_mlp_kernel<<<(NV*NPIX*4) / 128, 128>>>(depth_values, out);
    combine_kernel<<<(BDHW + 255) / 256, 256>>>();
    conv_softmax_kernel<<<(NPIX + 127) / 128, 128>>>(depth_values, out);
}

// round 5
// speedup vs baseline: 1.4781x; 1.1313x over previous
#include <cuda_runtime.h>
#include <math.h>

// Fixed problem shapes
#define BB 2
#define VV 3
#define CC 16
#define HH 128
#define WW 160
#define DD 48
#define HWW (HH*WW)            // 20480
#define NPIX (BB*HWW)          // 40960
#define BDHW (BB*DD*HWW)       // 1966080
#define NV (VV-1)              // 2 source views

// Output layout
#define OFF_DEPTH 0
#define OFF_CONF  (NPIX)
#define OFF_PROB  (2*NPIX)
#define OFF_VW    (2*NPIX + BDHW)

// -------- scratch --------
__device__ float g_feat_t[(size_t)BB*VV*HWW*CC];   // [b][v][h][w][c]
__device__ float g_sim[(size_t)NV*BDHW];           // [view][b][d][h][w]
__device__ float g_vw[(size_t)NV*NPIX];            // [view][b][h][w]
__device__ float g_simil[BDHW];
__device__ float g_proj[NV*BB*12];
__device__ float g_mlp[177];
__device__ float g_reg[28];

// ======================= prep =======================
__device__ void mat4_mul(const double* A, const double* B, double* Cm) {
    for (int r = 0; r < 4; r++)
        for (int c = 0; c < 4; c++) {
            double s = 0.0;
            for (int k = 0; k < 4; k++) s += A[r*4+k] * B[k*4+c];
            Cm[r*4+c] = s;
        }
}

__device__ void compose_proj(const float* p, double* out) {
    const float* E = p;
    const float* K = p + 16;
    for (int i = 0; i < 16; i++) out[i] = (double)E[i];
    for (int r = 0; r < 3; r++)
        for (int c = 0; c < 4; c++) {
            double s = 0.0;
            for (int k = 0; k < 3; k++) s += (double)K[r*4+k] * (double)E[k*4+c];
            out[r*4+c] = s;
        }
}

__device__ void inv4(const double* A, double* out) {
    double M[4][8];
    for (int i = 0; i < 4; i++)
        for (int j = 0; j < 4; j++) { M[i][j] = A[i*4+j]; M[i][4+j] = (i == j) ? 1.0 : 0.0; }
    for (int col = 0; col < 4; col++) {
        int piv = col;
        for (int r = col + 1; r < 4; r++)
            if (fabs(M[r][col]) > fabs(M[piv][col])) piv = r;
        if (piv != col)
            for (int j = 0; j < 8; j++) { double t = M[col][j]; M[col][j] = M[piv][j]; M[piv][j] = t; }
        double pv = M[col][col];
        for (int j = 0; j < 8; j++) M[col][j] /= pv;
        for (int r = 0; r < 4; r++) {
            if (r == col) continue;
            double f = M[r][col];
            for (int j = 0; j < 8; j++) M[r][j] -= f * M[col][j];
        }
    }
    for (int i = 0; i < 4; i++)
        for (int j = 0; j < 4; j++) out[i*4+j] = M[i][4+j];
}

__global__ void prep_kernel(const float* proj,
                            const float* w0, const float* g0, const float* b0,
                            const float* m0, const float* v0,
                            const float* w1, const float* g1, const float* b1,
                            const float* m1, const float* v1,
                            const float* w2, const float* b2,
                            const float* reg_w, const float* reg_b) {
    if (blockIdx.x != 0 || threadIdx.x != 0) return;
    for (int b = 0; b < BB; b++) {
        double refc[16], refi[16];
        compose_proj(proj + (size_t)(b*VV + 0)*2*16, refc);
        inv4(refc, refi);
        for (int v = 1; v < VV; v++) {
            double srcc[16], P[16];
            compose_proj(proj + (size_t)(b*VV + v)*2*16, srcc);
            mat4_mul(srcc, refi, P);
            float* dst = g_proj + ((v-1)*BB + b)*12;
            for (int r = 0; r < 3; r++)
                for (int c = 0; c < 3; c++) dst[r*3+c] = (float)P[r*4+c];
            dst[9]  = (float)P[0*4+3];
            dst[10] = (float)P[1*4+3];
            dst[11] = (float)P[2*4+3];
        }
    }
    for (int o = 0; o < 16; o++) {
        double s = (double)g0[o] / sqrt((double)v0[o] + 1e-5);
        g_mlp[o]      = (float)((double)w0[o] * s);
        g_mlp[16 + o] = (float)((double)b0[o] - (double)m0[o] * s);
    }
    for (int j = 0; j < 8; j++) {
        double s = (double)g1[j] / sqrt((double)v1[j] + 1e-5);
        for (int o = 0; o < 16; o++)
            g_mlp[32 + j*16 + o] = (float)((double)w1[j*16+o] * s);
        g_mlp[160 + j] = (float)((double)b1[j] - (double)m1[j] * s);
        g_mlp[168 + j] = w2[j];
    }
    g_mlp[176] = b2[0];
    for (int k = 0; k < 27; k++) g_reg[k] = reg_w[k];
    g_reg[27] = reg_b[0];
}

// ======================= feature transpose to [b][v][h][w][c] =======================
__global__ void transpose_kernel(const float* __restrict__ feat) {
    int idx = blockIdx.x * blockDim.x + threadIdx.x;
    if (idx >= BB*VV*HWW) return;
    int p  = idx % HWW;
    int bv = idx / HWW;
    const float* src = feat + (size_t)bv * CC * HWW + p;
    float v[CC];
#pragma unroll
    for (int c = 0; c < CC; c++) v[c] = src[(size_t)c * HWW];
    float4* dst = (float4*)(g_feat_t + ((size_t)bv * HWW + p) * CC);
    dst[0] = make_float4(v[0],  v[1],  v[2],  v[3]);
    dst[1] = make_float4(v[4],  v[5],  v[6],  v[7]);
    dst[2] = make_float4(v[8],  v[9],  v[10], v[11]);
    dst[3] = make_float4(v[12], v[13], v[14], v[15]);
}

// helper: coords for one depth
struct Coords {
    float x0f, y0f, fx, fy;
    int ix0, ix1, iy0, iy1;
    float vx0, vx1, vy0, vy1;
};
__device__ __forceinline__ Coords proj_coords(float dep, float rx, float ry, float rz,
                                              float tx, float ty, float tz) {
    Coords c;
    float X = fmaf(rx, dep, tx);
    float Y = fmaf(ry, dep, ty);
    float Z = fmaf(rz, dep, tz);
    float px = X / Z;            // exact IEEE division (argmax-sensitive)
    float py = Y / Z;
    c.x0f = floorf(px); c.y0f = floorf(py);
    c.fx = px - c.x0f;  c.fy = py - c.y0f;
    c.vx0 = (c.x0f >= 0.f       && c.x0f       <= (float)(WW-1)) ? 1.f : 0.f;
    c.vx1 = (c.x0f + 1.f >= 0.f && c.x0f + 1.f <= (float)(WW-1)) ? 1.f : 0.f;
    c.vy0 = (c.y0f >= 0.f       && c.y0f       <= (float)(HH-1)) ? 1.f : 0.f;
    c.vy1 = (c.y0f + 1.f >= 0.f && c.y0f + 1.f <= (float)(HH-1)) ? 1.f : 0.f;
    c.ix0 = (int)fminf(fmaxf(c.x0f,       0.f), (float)(WW-1));
    c.ix1 = (int)fminf(fmaxf(c.x0f + 1.f, 0.f), (float)(WW-1));
    c.iy0 = (int)fminf(fmaxf(c.y0f,       0.f), (float)(HH-1));
    c.iy1 = (int)fminf(fmaxf(c.y0f + 1.f, 0.f), (float)(HH-1));
    return c;
}

// full 16-ch dot of corner feature against ref, grouped as ((q0+q1)+(q2+q3))
__device__ __forceinline__ float full_dot(const float* fp, const float* rp) {
    float part[4];
#pragma unroll
    for (int qq = 0; qq < 4; qq++) {
        float4 f = ((const float4*)fp)[qq];
        float4 r = ((const float4*)rp)[qq];
        part[qq] = fmaf(f.x, r.x, fmaf(f.y, r.y, fmaf(f.z, r.z, f.w * r.w)));
    }
    return (part[0] + part[1]) + (part[2] + part[3]);
}

// ======================= fused gather + sim + MLP =======================
// thread = (view, pixel, q). Setup: 4 q-lanes cooperatively compute the 4
// depth-invariant corner dots (butterfly-reduced to all lanes). Depth loop:
// lane q owns depths d = q + 4k -- no duplicated projection math, no per-depth
// shfl. Guarded per-lane slow path recomputes dots if the corner ever moves.
__global__ void gather_mlp_kernel(const float* __restrict__ depth_values,
                                  float* __restrict__ out) {
    __shared__ float s_mlp[177];
    for (int i = threadIdx.x; i < 177; i += blockDim.x) s_mlp[i] = g_mlp[i];
    __syncthreads();

    int tid = blockIdx.x * blockDim.x + threadIdx.x;   // NV*NPIX*4, multiple of 128
    int q  = tid & 3;
    int vp = tid >> 2;
    int view = 1 + vp / NPIX;
    int pid  = vp % NPIX;
    int b = pid / HWW;
    int p = pid - b * HWW;
    int h = p / WW;
    int w = p - h * WW;

    const float* refp = g_feat_t + ((size_t)(b*VV + 0) * HWW + p) * CC;
    float4 rq = ((const float4*)refp)[q];

    const float* pr = g_proj + ((view-1)*BB + b) * 12;
    float fw = (float)w, fh = (float)h;
    float rx = pr[0]*fw + pr[1]*fh + pr[2];
    float ry = pr[3]*fw + pr[4]*fh + pr[5];
    float rz = pr[6]*fw + pr[7]*fh + pr[8];
    float tx = pr[9], ty = pr[10], tz = pr[11];

    const float* src = g_feat_t + (size_t)(b*VV + view) * HWW * CC;
    const float* dv  = depth_values + (size_t)b * DD * HWW + p;
    float* simout    = g_sim + (size_t)(view-1) * BDHW + (size_t)b * DD * HWW + p;

    // ---- setup: cooperative corner dots at the first depth's corner ----
    float cx0f, cy0f;            // cached (unclamped) corner identity
    float d00, d10, d01, d11;    // depth-invariant corner dots (all lanes)
    {
        float dep0 = __ldg(dv);
        Coords c = proj_coords(dep0, rx, ry, rz, tx, ty, tz);
        cx0f = c.x0f; cy0f = c.y0f;
        float4 f00 = ((const float4*)(src + ((size_t)(c.iy0*WW + c.ix0)) * CC))[q];
        float4 f10 = ((const float4*)(src + ((size_t)(c.iy0*WW + c.ix1)) * CC))[q];
        float4 f01 = ((const float4*)(src + ((size_t)(c.iy1*WW + c.ix0)) * CC))[q];
        float4 f11 = ((const float4*)(src + ((size_t)(c.iy1*WW + c.ix1)) * CC))[q];
        d00 = fmaf(f00.x, rq.x, fmaf(f00.y, rq.y, fmaf(f00.z, rq.z, f00.w * rq.w)));
        d10 = fmaf(f10.x, rq.x, fmaf(f10.y, rq.y, fmaf(f10.z, rq.z, f10.w * rq.w)));
        d01 = fmaf(f01.x, rq.x, fmaf(f01.y, rq.y, fmaf(f01.z, rq.z, f01.w * rq.w)));
        d11 = fmaf(f11.x, rq.x, fmaf(f11.y, rq.y, fmaf(f11.z, rq.z, f11.w * rq.w)));
        // butterfly: ((q0+q1)+(q2+q3)) to all 4 lanes
        d00 += __shfl_xor_sync(0xffffffffu, d00, 1);
        d10 += __shfl_xor_sync(0xffffffffu, d10, 1);
        d01 += __shfl_xor_sync(0xffffffffu, d01, 1);
        d11 += __shfl_xor_sync(0xffffffffu, d11, 1);
        d00 += __shfl_xor_sync(0xffffffffu, d00, 2);
        d10 += __shfl_xor_sync(0xffffffffu, d10, 2);
        d01 += __shfl_xor_sync(0xffffffffu, d01, 2);
        d11 += __shfl_xor_sync(0xffffffffu, d11, 2);
    }

    float omax = -3.4e38f;

    // ---- depth loop: lane q owns depths q, q+4, ..., q+44 ----
#pragma unroll 1
    for (int k = 0; k < DD/4; k++) {
        int d = q + 4*k;
        float dep = __ldg(dv + (size_t)d * HWW);
        Coords c = proj_coords(dep, rx, ry, rz, tx, ty, tz);

        if (c.x0f != cx0f || c.y0f != cy0f) {
            // rare: corner moved -- recompute all 4 dots for this lane
            cx0f = c.x0f; cy0f = c.y0f;
            d00 = full_dot(src + ((size_t)(c.iy0*WW + c.ix0)) * CC, refp);
            d10 = full_dot(src + ((size_t)(c.iy0*WW + c.ix1)) * CC, refp);
            d01 = full_dot(src + ((size_t)(c.iy1*WW + c.ix0)) * CC, refp);
            d11 = full_dot(src + ((size_t)(c.iy1*WW + c.ix1)) * CC, refp);
        }

        float w00 = (1.f - c.fx) * (1.f - c.fy) * (c.vx0 * c.vy0);
        float w10 = c.fx * (1.f - c.fy) * (c.vx1 * c.vy0);
        float w01 = (1.f - c.fx) * c.fy * (c.vx0 * c.vy1);
        float w11 = c.fx * c.fy * (c.vx1 * c.vy1);

        float sim = fmaf(w00, d00, fmaf(w10, d10, fmaf(w01, d01, w11 * d11))) * 0.0625f;
        simout[(size_t)d * HWW] = sim;

        // MLP (BN folded): 1 -> 16 -> 8 -> 1
        float a1[8];
#pragma unroll
        for (int j = 0; j < 8; j++) a1[j] = s_mlp[160 + j];
#pragma unroll
        for (int o = 0; o < 16; o++) {
            float h0 = fmaxf(0.f, fmaf(s_mlp[o], sim, s_mlp[16 + o]));
#pragma unroll
            for (int j = 0; j < 8; j++) a1[j] = fmaf(s_mlp[32 + j*16 + o], h0, a1[j]);
        }
        float ov = s_mlp[176];
#pragma unroll
        for (int j = 0; j < 8; j++) ov = fmaf(s_mlp[168 + j], fmaxf(0.f, a1[j]), ov);
        omax = fmaxf(omax, ov);
    }

    // max over the 4 q-lanes
    omax = fmaxf(omax, __shfl_xor_sync(0xffffffffu, omax, 1));
    omax = fmaxf(omax, __shfl_xor_sync(0xffffffffu, omax, 2));

    if (q == 0) {
        float vw = 1.f / (1.f + expf(-omax));    // exact sigmoid
        g_vw[(size_t)(view-1) * NPIX + pid] = vw;
        out[OFF_VW + (size_t)b * NV * HWW + (size_t)(view-1) * HWW + p] = vw;
    }
}

// ======================= weighted combine =======================
__global__ void combine_kernel() {
    int idx = blockIdx.x * blockDim.x + threadIdx.x;   // over BDHW
    if (idx >= BDHW) return;
    int b = idx / (DD * HWW);
    int p = idx % HWW;
    float w0v = g_vw[(size_t)b * HWW + p];
    float w1v = g_vw[(size_t)NPIX + (size_t)b * HWW + p];
    float s0 = g_sim[idx];
    float s1 = g_sim[(size_t)BDHW + idx];
    g_simil[idx] = (s0 * w0v + s1 * w1v) / (1e-5f + w0v + w1v);   // exact division
}

// ======================= fused 3x3x3 conv + softmax + argmax + outputs =======================
__global__ void conv_softmax_kernel(const float* __restrict__ depth_values, float* __restrict__ out) {
    __shared__ float s_k[28];
    if (threadIdx.x < 28) s_k[threadIdx.x] = g_reg[threadIdx.x];
    __syncthreads();

    int pid = blockIdx.x * blockDim.x + threadIdx.x;
    if (pid >= NPIX) return;
    int b = pid / HWW;
    int p = pid - b * HWW;
    int h = p / WW;
    int w = p - h * WW;

    float c[DD];
    float bias = s_k[27];
#pragma unroll
    for (int d = 0; d < DD; d++) c[d] = bias;

    bool wl = (w > 0), wr = (w < WW - 1);
#pragma unroll
    for (int dp = 0; dp < DD; dp++) {
        const float* base = g_simil + (size_t)(b*DD + dp) * HWW;
        float n[9];
#pragma unroll
        for (int dy = 0; dy < 3; dy++) {
            int hh = h + dy - 1;
            bool vy = (unsigned)hh < (unsigned)HH;
            const float* rowp = base + hh * WW + w;
            n[dy*3+0] = (vy && wl) ? rowp[-1] : 0.f;
            n[dy*3+1] = vy ? rowp[0] : 0.f;
            n[dy*3+2] = (vy && wr) ? rowp[1] : 0.f;
        }
#pragma unroll
        for (int dz = 0; dz < 3; dz++) {
            int od = dp + 1 - dz;
            if (od < 0 || od >= DD) continue;
            float acc = 0.f;
#pragma unroll
            for (int i = 0; i < 9; i++) acc = fmaf(s_k[dz*9+i], n[i], acc);
            c[od] += acc;
        }
    }

    float m = c[0]; int am = 0;
#pragma unroll
    for (int d = 1; d < DD; d++) if (c[d] > m) { m = c[d]; am = d; }
    float sum = 0.f;
#pragma unroll
    for (int d = 0; d < DD; d++) { float e = __expf(c[d] - m); c[d] = e; sum += e; }
    float inv = __fdividef(1.f, sum);
    float* pp = out + OFF_PROB + (size_t)b * DD * HWW + p;
#pragma unroll
    for (int d = 0; d < DD; d++) pp[(size_t)d * HWW] = c[d] * inv;
    out[OFF_DEPTH + pid] = depth_values[(size_t)b * DD * HWW + (size_t)am * HWW + p];
    out[OFF_CONF + pid] = inv;
}

// ======================= launch =======================
extern "C" void kernel_launch(void* const* d_in, const int* in_sizes, int n_in,
                              void* d_out, int out_size) {
    const float* features     = (const float*)d_in[0];
    const float* proj         = (const float*)d_in[1];
    const float* depth_values = (const float*)d_in[2];
    const float* w0 = (const float*)d_in[3];
    const float* g0 = (const float*)d_in[4];
    const float* b0 = (const float*)d_in[5];
    const float* m0 = (const float*)d_in[6];
    const float* v0 = (const float*)d_in[7];
    const float* w1 = (const float*)d_in[8];
    const float* g1 = (const float*)d_in[9];
    const float* b1 = (const float*)d_in[10];
    const float* m1 = (const float*)d_in[11];
    const float* v1 = (const float*)d_in[12];
    const float* w2 = (const float*)d_in[13];
    const float* b2 = (const float*)d_in[14];
    const float* reg_w = (const float*)d_in[15];
    const float* reg_b = (const float*)d_in[16];
    float* out = (float*)d_out;

    transpose_kernel<<<(BB*VV*HWW + 255) / 256, 256>>>(features);
    prep_kernel<<<1, 32>>>(proj, w0, g0, b0, m0, v0, w1, g1, b1, m1, v1, w2, b2, reg_w, reg_b);
    gather_mlp_kernel<<<(NV*NPIX*4) / 128, 128>>>(depth_values, out);
    combine_kernel<<<(BDHW + 255) / 256, 256>>>();
    conv_softmax_kernel<<<(NPIX + 127) / 128, 128>>>(depth_values, out);
}